// round 3
// baseline (speedup 1.0000x reference)
#include <cuda_runtime.h>
#include <cstdint>

#define S 128
#define C 32
#define NN 4096
#define T 512

// ---------------- scratch (device globals; no allocation) ----------------
__device__ __align__(256) float g_P[S * NN];      // exp(log_softmax(emission))  [S,N]
__device__ __align__(256) float g_Tp[2][S * S];   // transition-power double buffer
__device__ __align__(256) float g_p[T * C * S];   // p_t = exp(h_t) for all t    [T,C,S]
__device__ __align__(256) float g_wexp[T * C];    // exp(log_softmax(weights))   [T,C]

__device__ __forceinline__ float warpRedMax(float v) {
#pragma unroll
    for (int o = 16; o > 0; o >>= 1) v = fmaxf(v, __shfl_xor_sync(0xffffffffu, v, o));
    return v;
}
__device__ __forceinline__ float warpRedSum(float v) {
#pragma unroll
    for (int o = 16; o > 0; o >>= 1) v += __shfl_xor_sync(0xffffffffu, v, o);
    return v;
}

// ---------------- row-wise log_softmax (+optional exp to a device-global) ----
// exp_dst selector (resolved in DEVICE code; __device__ globals are not
// addressable from host): 0 -> g_P, 1 -> g_wexp, 2 -> g_p, 3 -> g_Tp[0],
// negative -> no exp output. dlog may be null.
__global__ void softmax_rows(const float* __restrict__ src, float* __restrict__ dlog,
                             int exp_dst, int ncols) {
    float* dexp = nullptr;
    if (exp_dst == 0) dexp = g_P;
    else if (exp_dst == 1) dexp = g_wexp;
    else if (exp_dst == 2) dexp = g_p;
    else if (exp_dst == 3) dexp = g_Tp[0];

    int row = blockIdx.x;
    const float* p = src + (size_t)row * ncols;
    int tid = threadIdx.x, lane = tid & 31, wid = tid >> 5;
    __shared__ float red[8];

    float m = -3.4e38f;
    for (int i = tid; i < ncols; i += blockDim.x) m = fmaxf(m, p[i]);
    m = warpRedMax(m);
    if (lane == 0) red[wid] = m;
    __syncthreads();
    if (wid == 0) {
        float v = (lane < 8) ? red[lane] : -3.4e38f;
        v = warpRedMax(v);
        if (lane == 0) red[0] = v;
    }
    __syncthreads();
    m = red[0];
    __syncthreads();

    float s = 0.f;
    for (int i = tid; i < ncols; i += blockDim.x) s += __expf(p[i] - m);
    s = warpRedSum(s);
    if (lane == 0) red[wid] = s;
    __syncthreads();
    if (wid == 0) {
        float v = (lane < 8) ? red[lane] : 0.f;
        v = warpRedSum(v);
        if (lane == 0) red[0] = v;
    }
    __syncthreads();
    float lse = m + __logf(red[0]);

    for (int i = tid; i < ncols; i += blockDim.x) {
        float v = p[i] - lse;
        if (dlog) dlog[(size_t)row * ncols + i] = v;
        if (dexp) dexp[(size_t)row * ncols + i] = __expf(v);
    }
}

// ---------------- doubling level: fill p[L..2L-1] and square T^L ----------------
// Blocks [0,L): p[L+b] = p[b] @ Tcur (32x128 @ 128x128)
// Blocks [L,L+4): rows 32*rb..32*rb+31 of Tnext = Tcur @ Tcur
__global__ __launch_bounds__(256) void expand_level(int L, int curIdx) {
    extern __shared__ float sm[];
    float* sA = sm;              // 32*128
    float* sB = sm + 32 * S;     // 128*128
    int tid = threadIdx.x, lane = tid & 31, wid = tid >> 5;
    int b = blockIdx.x;

    const float* Tcur = g_Tp[curIdx];
    float* Tnext = g_Tp[curIdx ^ 1];

    const float* A;
    float* O;
    if (b < L) {
        A = g_p + (size_t)b * C * S;
        O = g_p + (size_t)(L + b) * C * S;
    } else {
        int rb = b - L;
        A = Tcur + rb * 32 * S;
        O = Tnext + rb * 32 * S;
    }

    const float4* B4 = reinterpret_cast<const float4*>(Tcur);
    float4* sB4 = reinterpret_cast<float4*>(sB);
    for (int i = tid; i < S * S / 4; i += 256) sB4[i] = B4[i];
    const float4* A4 = reinterpret_cast<const float4*>(A);
    float4* sA4 = reinterpret_cast<float4*>(sA);
    for (int i = tid; i < 32 * S / 4; i += 256) sA4[i] = A4[i];
    __syncthreads();

    int c0 = wid * 4, n0 = lane * 4;
    float acc[4][4] = {};
#pragma unroll 8
    for (int s = 0; s < S; s++) {
        float4 bv = *reinterpret_cast<const float4*>(&sB[s * S + n0]);
#pragma unroll
        for (int j = 0; j < 4; j++) {
            float a = sA[(c0 + j) * S + s];
            acc[j][0] = fmaf(a, bv.x, acc[j][0]);
            acc[j][1] = fmaf(a, bv.y, acc[j][1]);
            acc[j][2] = fmaf(a, bv.z, acc[j][2]);
            acc[j][3] = fmaf(a, bv.w, acc[j][3]);
        }
    }
#pragma unroll
    for (int j = 0; j < 4; j++) {
        *reinterpret_cast<float4*>(&O[(c0 + j) * S + n0]) =
            make_float4(acc[j][0], acc[j][1], acc[j][2], acc[j][3]);
    }
}

// ---------------- log of hidden probs (output 3) ----------------
__global__ void log_kernel(float* __restrict__ o3) {
    int i = blockIdx.x * blockDim.x + threadIdx.x;
    o3[i] = __logf(g_p[i]);
}

// ---------------- big fused GEMM + logs + chain reduction ----------------
// CTA = (n-tile of 256, t). q[c,n] = sum_s p_t[c,s] * P[s,n]
// out2 = log q ; out1[t,n] = log(sum_c q * wexp[t,c])
__global__ __launch_bounds__(256) void big_kernel(float* __restrict__ o1, float* __restrict__ o2) {
    extern __shared__ float sm[];
    float* sA = sm;                 // 32*128  = 4096
    float* sP = sm + 4096;          // 128*256 = 32768
    float* sObs = sP + 32768;       // 8*256   = 2048
    int tid = threadIdx.x, lane = tid & 31, wid = tid >> 5;
    int t = blockIdx.y;
    int nb = blockIdx.x * 256;

    const float4* A4 = reinterpret_cast<const float4*>(g_p + (size_t)t * C * S);
    float4* sA4 = reinterpret_cast<float4*>(sA);
    for (int i = tid; i < C * S / 4; i += 256) sA4[i] = A4[i];

    const float4* P4 = reinterpret_cast<const float4*>(g_P);
    float4* sP4 = reinterpret_cast<float4*>(sP);
    int nb4 = nb >> 2;
    for (int i = tid; i < S * 64; i += 256) {
        int s = i >> 6, j = i & 63;
        sP4[s * 64 + j] = P4[s * (NN / 4) + nb4 + j];
    }
    __syncthreads();

    int c0 = wid * 4;
    float acc[4][8] = {};
#pragma unroll 4
    for (int s = 0; s < S; s++) {
        float4 b0 = *reinterpret_cast<const float4*>(&sP[s * 256 + lane * 4]);
        float4 b1 = *reinterpret_cast<const float4*>(&sP[s * 256 + 128 + lane * 4]);
#pragma unroll
        for (int j = 0; j < 4; j++) {
            float a = sA[(c0 + j) * S + s];
            acc[j][0] = fmaf(a, b0.x, acc[j][0]);
            acc[j][1] = fmaf(a, b0.y, acc[j][1]);
            acc[j][2] = fmaf(a, b0.z, acc[j][2]);
            acc[j][3] = fmaf(a, b0.w, acc[j][3]);
            acc[j][4] = fmaf(a, b1.x, acc[j][4]);
            acc[j][5] = fmaf(a, b1.y, acc[j][5]);
            acc[j][6] = fmaf(a, b1.z, acc[j][6]);
            acc[j][7] = fmaf(a, b1.w, acc[j][7]);
        }
    }

    float w[4];
#pragma unroll
    for (int j = 0; j < 4; j++) w[j] = g_wexp[t * C + c0 + j];

    float pa[4] = {0.f, 0.f, 0.f, 0.f};
    float pb[4] = {0.f, 0.f, 0.f, 0.f};
#pragma unroll
    for (int j = 0; j < 4; j++) {
        size_t base = ((size_t)(t * C + c0 + j)) * NN + nb;
        float4 la = make_float4(__logf(acc[j][0]), __logf(acc[j][1]),
                                __logf(acc[j][2]), __logf(acc[j][3]));
        *reinterpret_cast<float4*>(&o2[base + lane * 4]) = la;
        float4 lb = make_float4(__logf(acc[j][4]), __logf(acc[j][5]),
                                __logf(acc[j][6]), __logf(acc[j][7]));
        *reinterpret_cast<float4*>(&o2[base + 128 + lane * 4]) = lb;
#pragma unroll
        for (int k = 0; k < 4; k++) {
            pa[k] = fmaf(acc[j][k], w[j], pa[k]);
            pb[k] = fmaf(acc[j][4 + k], w[j], pb[k]);
        }
    }
    // deterministic cross-warp reduction (no atomics)
    *reinterpret_cast<float4*>(&sObs[wid * 256 + lane * 4]) = make_float4(pa[0], pa[1], pa[2], pa[3]);
    *reinterpret_cast<float4*>(&sObs[wid * 256 + 128 + lane * 4]) = make_float4(pb[0], pb[1], pb[2], pb[3]);
    __syncthreads();
    {
        int n = tid;
        float ssum = 0.f;
#pragma unroll
        for (int w8 = 0; w8 < 8; w8++) ssum += sObs[w8 * 256 + n];
        o1[(size_t)t * NN + nb + n] = __logf(ssum);
    }
}

// ---------------- launch ----------------
extern "C" void kernel_launch(void* const* d_in, const int* in_sizes, int n_in,
                              void* d_out, int out_size) {
    (void)in_sizes; (void)n_in; (void)out_size;
    const float* init    = (const float*)d_in[0];   // [32,128]
    const float* weights = (const float*)d_in[1];   // [512,32]
    const float* emis    = (const float*)d_in[2];   // [128,4096]
    const float* trans   = (const float*)d_in[3];   // [128,128]

    float* out = (float*)d_out;
    float* o1 = out;                       // [512,4096]
    float* o2 = o1 + (size_t)T * NN;       // [512,32,4096]
    float* o3 = o2 + (size_t)T * C * NN;   // [512,32,128]
    float* o4 = o3 + (size_t)T * C * S;    // [128,4096]
    float* o5 = o4 + (size_t)S * NN;       // [512,32]

    const int expandSmem = (32 * S + S * S) * 4;              // 81920
    const int bigSmem    = (4096 + 32768 + 2048) * 4;         // 155648
    cudaFuncSetAttribute(expand_level, cudaFuncAttributeMaxDynamicSharedMemorySize, expandSmem);
    cudaFuncSetAttribute(big_kernel,   cudaFuncAttributeMaxDynamicSharedMemorySize, bigSmem);

    // preprocess: log_softmax everything, keep exp() in device-global scratch
    softmax_rows<<<S, 256>>>(emis,    o4,      0, NN);   // g_P
    softmax_rows<<<T, 256>>>(weights, o5,      1, C);    // g_wexp
    softmax_rows<<<C, 256>>>(init,    nullptr, 2, S);    // g_p (p_0)
    softmax_rows<<<S, 256>>>(trans,   nullptr, 3, S);    // g_Tp[0] (T^1)

    // doubling recurrence: 9 levels
    for (int k = 0; k < 9; k++) {
        int L = 1 << k;
        int doSquare = (k < 8) ? 1 : 0;
        int grid = L + (doSquare ? 4 : 0);
        expand_level<<<grid, 256, expandSmem>>>(L, k & 1);
    }

    // output 3: h_t = log p_t
    log_kernel<<<(T * C * S) / 1024, 1024>>>(o3);

    // big fused GEMM + logs + chain reduction (outputs 1, 2)
    dim3 grid(NN / 256, T);
    big_kernel<<<grid, 256, bigSmem>>>(o1, o2);
}

// round 6
// speedup vs baseline: 1.5048x; 1.5048x over previous
#include <cuda_runtime.h>
#include <cuda_bf16.h>
#include <cstdint>

#define S 128
#define C 32
#define NN 4096
#define T 512

extern __shared__ char dyn_smem[];

// ---------------- scratch (device globals; no allocation) ----------------
__device__ __align__(256) float g_P[S * NN];      // exp(log_softmax(emission))  [S,N]
__device__ __align__(256) float g_Tp[2][S * S];   // transition-power double buffer
__device__ __align__(256) float g_p[T * C * S];   // p_t = exp(h_t)              [T*C, S]
__device__ __align__(256) float g_wexp[T * C];    // exp(log_softmax(weights))   [T,C]
__device__ __align__(256) __nv_bfloat16 g_pA_hi[T * C * S];
__device__ __align__(256) __nv_bfloat16 g_pA_lo[T * C * S];
__device__ __align__(256) __nv_bfloat16 g_PT_hi[NN * S];   // P^T [n, s] K-contig
__device__ __align__(256) __nv_bfloat16 g_PT_lo[NN * S];

// ---------------- helpers ----------------
__device__ __forceinline__ uint32_t smem_u32(const void* p) {
    uint32_t a;
    asm("{ .reg .u64 t; cvta.to.shared.u64 t, %1; cvt.u32.u64 %0, t; }" : "=r"(a) : "l"(p));
    return a;
}
__device__ __forceinline__ void ldsm_x4(uint32_t addr, uint32_t& r0, uint32_t& r1,
                                        uint32_t& r2, uint32_t& r3) {
    asm volatile("ldmatrix.sync.aligned.m8n8.x4.shared.b16 {%0,%1,%2,%3}, [%4];"
                 : "=r"(r0), "=r"(r1), "=r"(r2), "=r"(r3) : "r"(addr));
}
__device__ __forceinline__ void mma16816(float* d, const uint32_t* a, const uint32_t* b) {
    asm volatile(
        "mma.sync.aligned.m16n8k16.row.col.f32.bf16.bf16.f32 "
        "{%0,%1,%2,%3},{%4,%5,%6,%7},{%8,%9},{%0,%1,%2,%3};"
        : "+f"(d[0]), "+f"(d[1]), "+f"(d[2]), "+f"(d[3])
        : "r"(a[0]), "r"(a[1]), "r"(a[2]), "r"(a[3]), "r"(b[0]), "r"(b[1]));
}
__device__ __forceinline__ float warpRedMax(float v) {
#pragma unroll
    for (int o = 16; o > 0; o >>= 1) v = fmaxf(v, __shfl_xor_sync(0xffffffffu, v, o));
    return v;
}
__device__ __forceinline__ float warpRedSum(float v) {
#pragma unroll
    for (int o = 16; o > 0; o >>= 1) v += __shfl_xor_sync(0xffffffffu, v, o);
    return v;
}

// ---------------- row-wise log_softmax (+optional exp to device-global) ----
__global__ void softmax_rows(const float* __restrict__ src, float* __restrict__ dlog,
                             int exp_dst, int ncols) {
    float* dexp = nullptr;
    if (exp_dst == 0) dexp = g_P;
    else if (exp_dst == 1) dexp = g_wexp;
    else if (exp_dst == 2) dexp = g_p;
    else if (exp_dst == 3) dexp = g_Tp[0];

    int row = blockIdx.x;
    const float* p = src + (size_t)row * ncols;
    int tid = threadIdx.x, lane = tid & 31, wid = tid >> 5;
    __shared__ float red[8];

    float m = -3.4e38f;
    for (int i = tid; i < ncols; i += blockDim.x) m = fmaxf(m, p[i]);
    m = warpRedMax(m);
    if (lane == 0) red[wid] = m;
    __syncthreads();
    if (wid == 0) {
        float v = (lane < 8) ? red[lane] : -3.4e38f;
        v = warpRedMax(v);
        if (lane == 0) red[0] = v;
    }
    __syncthreads();
    m = red[0];
    __syncthreads();

    float s = 0.f;
    for (int i = tid; i < ncols; i += blockDim.x) s += __expf(p[i] - m);
    s = warpRedSum(s);
    if (lane == 0) red[wid] = s;
    __syncthreads();
    if (wid == 0) {
        float v = (lane < 8) ? red[lane] : 0.f;
        v = warpRedSum(v);
        if (lane == 0) red[0] = v;
    }
    __syncthreads();
    float lse = m + __logf(red[0]);

    for (int i = tid; i < ncols; i += blockDim.x) {
        float v = p[i] - lse;
        if (dlog) dlog[(size_t)row * ncols + i] = v;
        if (dexp) dexp[(size_t)row * ncols + i] = __expf(v);
    }
}

// ---------------- doubling level (verified round 3) ----------------
__global__ __launch_bounds__(256) void expand_level(int L, int curIdx) {
    float* smf = reinterpret_cast<float*>(dyn_smem);
    float* sA = smf;
    float* sB = smf + 32 * S;
    int tid = threadIdx.x, lane = tid & 31, wid = tid >> 5;
    int b = blockIdx.x;

    const float* Tcur = g_Tp[curIdx];
    float* Tnext = g_Tp[curIdx ^ 1];

    const float* A;
    float* O;
    if (b < L) {
        A = g_p + (size_t)b * C * S;
        O = g_p + (size_t)(L + b) * C * S;
    } else {
        int rb = b - L;
        A = Tcur + rb * 32 * S;
        O = Tnext + rb * 32 * S;
    }

    const float4* B4 = reinterpret_cast<const float4*>(Tcur);
    float4* sB4 = reinterpret_cast<float4*>(sB);
    for (int i = tid; i < S * S / 4; i += 256) sB4[i] = B4[i];
    const float4* A4 = reinterpret_cast<const float4*>(A);
    float4* sA4 = reinterpret_cast<float4*>(sA);
    for (int i = tid; i < 32 * S / 4; i += 256) sA4[i] = A4[i];
    __syncthreads();

    int c0 = wid * 4, n0 = lane * 4;
    float acc[4][4] = {};
#pragma unroll 8
    for (int s = 0; s < S; s++) {
        float4 bv = *reinterpret_cast<const float4*>(&sB[s * S + n0]);
#pragma unroll
        for (int j = 0; j < 4; j++) {
            float a = sA[(c0 + j) * S + s];
            acc[j][0] = fmaf(a, bv.x, acc[j][0]);
            acc[j][1] = fmaf(a, bv.y, acc[j][1]);
            acc[j][2] = fmaf(a, bv.z, acc[j][2]);
            acc[j][3] = fmaf(a, bv.w, acc[j][3]);
        }
    }
#pragma unroll
    for (int j = 0; j < 4; j++) {
        *reinterpret_cast<float4*>(&O[(c0 + j) * S + n0]) =
            make_float4(acc[j][0], acc[j][1], acc[j][2], acc[j][3]);
    }
}

// ---------------- log of hidden probs (output 3) ----------------
__global__ void log_kernel(float* __restrict__ o3) {
    int i = blockIdx.x * blockDim.x + threadIdx.x;
    o3[i] = __logf(g_p[i]);
}

// ---------------- hi/lo split of p ----------------
__device__ __forceinline__ uint32_t pack2(float a, float b, float& ra, float& rb) {
    __nv_bfloat16 ha = __float2bfloat16_rn(a);
    __nv_bfloat16 hb = __float2bfloat16_rn(b);
    ra = a - __bfloat162float(ha);
    rb = b - __bfloat162float(hb);
    return (uint32_t)__bfloat16_as_ushort(ha) | ((uint32_t)__bfloat16_as_ushort(hb) << 16);
}
__global__ void convert_p() {
    int i = blockIdx.x * blockDim.x + threadIdx.x;   // over T*C*S/4
    float4 v = reinterpret_cast<const float4*>(g_p)[i];
    float r0, r1, r2, r3;
    uint32_t h0 = pack2(v.x, v.y, r0, r1);
    uint32_t h1 = pack2(v.z, v.w, r2, r3);
    float d0, d1, d2, d3;
    uint32_t l0 = pack2(r0, r1, d0, d1);
    uint32_t l1 = pack2(r2, r3, d2, d3);
    reinterpret_cast<uint2*>(g_pA_hi)[i] = make_uint2(h0, h1);
    reinterpret_cast<uint2*>(g_pA_lo)[i] = make_uint2(l0, l1);
}

// ---------------- transpose P [S,N] -> PT hi/lo [N,S] ----------------
__global__ void transpose_P() {
    __shared__ float ts[32][33];
    int n0 = blockIdx.x * 32, s0 = blockIdx.y * 32;
    int tx = threadIdx.x, ty = threadIdx.y;   // (32, 8)
#pragma unroll
    for (int r = 0; r < 4; r++)
        ts[ty + r * 8][tx] = g_P[(size_t)(s0 + ty + r * 8) * NN + n0 + tx];
    __syncthreads();
#pragma unroll
    for (int r = 0; r < 4; r++) {
        int nloc = ty + r * 8;
        float x = ts[tx][nloc];
        __nv_bfloat16 h = __float2bfloat16_rn(x);
        __nv_bfloat16 l = __float2bfloat16_rn(x - __bfloat162float(h));
        size_t idx = (size_t)(n0 + nloc) * S + s0 + tx;
        g_PT_hi[idx] = h;
        g_PT_lo[idx] = l;
    }
}

// ---------------- mma.sync GEMM + log epilogue + chain reduction ----------------
// CTA = (n-tile 128, t-quad). A rows = p rows [quad*128 .. +127] (row = tloc*32 + c).
// B rows = PT rows [nb .. nb+127]. D = Ah*Bh + Ah*Bl + Al*Bh (fp32 regs).
// Warp w: rows 32*(w&3) (one t, all chains) x cols 64*(w>>2).
static constexpr int PITCH = 272;                 // bytes per 128-bf16 row (+16B pad)
static constexpr int TILE = 128 * PITCH;          // 34816
static constexpr int MMA_SMEM = 4 * TILE;         // 139264 (Ah, Al, Bh, Bl)

__global__ __launch_bounds__(256, 1)
void mma_kernel(float* __restrict__ o1, float* __restrict__ o2) {
    char* sm = dyn_smem;
    uint32_t smb = smem_u32(sm);
    int tid = threadIdx.x, lane = tid & 31, wid = tid >> 5;
    int quad = blockIdx.y;
    int nb = blockIdx.x * 128;

    // ---- fill 4 tiles: row-major bf16, 272B pitch ----
    const uint4* srcAh = reinterpret_cast<const uint4*>(g_pA_hi) + (size_t)quad * 128 * 16;
    const uint4* srcAl = reinterpret_cast<const uint4*>(g_pA_lo) + (size_t)quad * 128 * 16;
    const uint4* srcBh = reinterpret_cast<const uint4*>(g_PT_hi) + (size_t)nb * 16;
    const uint4* srcBl = reinterpret_cast<const uint4*>(g_PT_lo) + (size_t)nb * 16;
#pragma unroll
    for (int it = 0; it < 8; it++) {
        int i = tid + it * 256;              // 0..2047 (= row*16 + chunk)
        int row = i >> 4, chunk = i & 15;
        int d = row * PITCH + chunk * 16;
        *reinterpret_cast<uint4*>(sm + 0 * TILE + d) = srcAh[i];
        *reinterpret_cast<uint4*>(sm + 1 * TILE + d) = srcAl[i];
        *reinterpret_cast<uint4*>(sm + 2 * TILE + d) = srcBh[i];
        *reinterpret_cast<uint4*>(sm + 3 * TILE + d) = srcBl[i];
    }
    __syncthreads();

    int mbase = (wid & 3) * 32;
    int nbL = (wid >> 2) * 64;

    // ldmatrix lane addressing
    int aRow = mbase + (lane & 15);
    int aKoff = (lane >> 4) << 4;                     // 0 or 16 bytes
    int bRow = nbL + ((lane >> 4) << 3) + (lane & 7); // n-row
    int bKoff = ((lane >> 3) & 1) << 4;               // 0 or 16 bytes

    float acc[2][8][4];
#pragma unroll
    for (int mt = 0; mt < 2; mt++)
#pragma unroll
        for (int nt = 0; nt < 8; nt++)
#pragma unroll
            for (int e = 0; e < 4; e++) acc[mt][nt][e] = 0.f;

    const int aTile[3] = {0, 0, 1};   // hi, hi, lo
    const int bTile[3] = {2, 3, 2};   // hi, lo, hi
#pragma unroll
    for (int pass = 0; pass < 3; pass++) {
        uint32_t Ab = smb + aTile[pass] * TILE;
        uint32_t Bb = smb + bTile[pass] * TILE;
#pragma unroll
        for (int k16 = 0; k16 < 8; k16++) {
            uint32_t a[2][4];
#pragma unroll
            for (int mt = 0; mt < 2; mt++)
                ldsm_x4(Ab + (aRow + mt * 16) * PITCH + k16 * 32 + aKoff,
                        a[mt][0], a[mt][1], a[mt][2], a[mt][3]);
            uint32_t b[8][2];
#pragma unroll
            for (int nt2 = 0; nt2 < 4; nt2++)
                ldsm_x4(Bb + (bRow + nt2 * 16) * PITCH + k16 * 32 + bKoff,
                        b[nt2 * 2][0], b[nt2 * 2][1], b[nt2 * 2 + 1][0], b[nt2 * 2 + 1][1]);
#pragma unroll
            for (int mt = 0; mt < 2; mt++)
#pragma unroll
                for (int nt = 0; nt < 8; nt++)
                    mma16816(acc[mt][nt], a[mt], b[nt]);
        }
    }

    // ---- epilogue: logs + o2 stores + chain-weight reduction ----
    int t = quad * 4 + (wid & 3);
    float wlane = g_wexp[t * C + lane];
    int r0 = lane >> 2;            // row-in-m16
    int cq = lane & 3;             // col pair selector

    float wr[2][2];                // [mt][half] chain weights for this thread's rows
#pragma unroll
    for (int mt = 0; mt < 2; mt++) {
        wr[mt][0] = __shfl_sync(0xffffffffu, wlane, mt * 16 + r0);
        wr[mt][1] = __shfl_sync(0xffffffffu, wlane, mt * 16 + r0 + 8);
    }

#pragma unroll
    for (int nt = 0; nt < 8; nt++) {
        int ncol = nb + nbL + nt * 8 + cq * 2;
        float v0 = 0.f, v1 = 0.f;
#pragma unroll
        for (int mt = 0; mt < 2; mt++) {
            int c0 = mt * 16 + r0, c1 = c0 + 8;
            float2 s0 = make_float2(__logf(acc[mt][nt][0]), __logf(acc[mt][nt][1]));
            float2 s1 = make_float2(__logf(acc[mt][nt][2]), __logf(acc[mt][nt][3]));
            *reinterpret_cast<float2*>(&o2[((size_t)(t * C + c0)) * NN + ncol]) = s0;
            *reinterpret_cast<float2*>(&o2[((size_t)(t * C + c1)) * NN + ncol]) = s1;
            v0 += acc[mt][nt][0] * wr[mt][0] + acc[mt][nt][2] * wr[mt][1];
            v1 += acc[mt][nt][1] * wr[mt][0] + acc[mt][nt][3] * wr[mt][1];
        }
#pragma unroll
        for (int o = 4; o < 32; o <<= 1) {
            v0 += __shfl_xor_sync(0xffffffffu, v0, o);
            v1 += __shfl_xor_sync(0xffffffffu, v1, o);
        }
        if (lane < 4) {
            int n = nb + nbL + nt * 8 + lane * 2;
            *reinterpret_cast<float2*>(&o1[(size_t)t * NN + n]) =
                make_float2(__logf(v0), __logf(v1));
        }
    }
}

// ---------------- launch ----------------
extern "C" void kernel_launch(void* const* d_in, const int* in_sizes, int n_in,
                              void* d_out, int out_size) {
    (void)in_sizes; (void)n_in; (void)out_size;
    const float* init    = (const float*)d_in[0];   // [32,128]
    const float* weights = (const float*)d_in[1];   // [512,32]
    const float* emis    = (const float*)d_in[2];   // [128,4096]
    const float* trans   = (const float*)d_in[3];   // [128,128]

    float* out = (float*)d_out;
    float* o1 = out;                       // [512,4096]
    float* o2 = o1 + (size_t)T * NN;       // [512,32,4096]
    float* o3 = o2 + (size_t)T * C * NN;   // [512,32,128]
    float* o4 = o3 + (size_t)T * C * S;    // [128,4096]
    float* o5 = o4 + (size_t)S * NN;       // [512,32]

    const int expandSmem = (32 * S + S * S) * 4;   // 81920
    cudaFuncSetAttribute(expand_level, cudaFuncAttributeMaxDynamicSharedMemorySize, expandSmem);
    cudaFuncSetAttribute(mma_kernel, cudaFuncAttributeMaxDynamicSharedMemorySize, MMA_SMEM);

    // preprocess: log_softmax everything, exp() into device-global scratch
    softmax_rows<<<S, 256>>>(emis,    o4,      0, NN);   // g_P
    softmax_rows<<<T, 256>>>(weights, o5,      1, C);    // g_wexp
    softmax_rows<<<C, 256>>>(init,    nullptr, 2, S);    // g_p (p_0)
    softmax_rows<<<S, 256>>>(trans,   nullptr, 3, S);    // g_Tp[0]

    // P^T hi/lo (only needs emission softmax done)
    transpose_P<<<dim3(NN / 32, S / 32), dim3(32, 8)>>>();

    // doubling recurrence: 9 levels
    for (int k = 0; k < 9; k++) {
        int L = 1 << k;
        int doSquare = (k < 8) ? 1 : 0;
        int grid = L + (doSquare ? 4 : 0);
        expand_level<<<grid, 256, expandSmem>>>(L, k & 1);
    }

    // output 3: h_t = log p_t
    log_kernel<<<(T * C * S) / 1024, 1024>>>(o3);

    // hi/lo split of p for the tensor-core GEMM
    convert_p<<<(T * C * S / 4) / 256, 256>>>();

    // mma.sync GEMM + log epilogue (outputs 1, 2)
    dim3 grid(NN / 128, T / 4);
    mma_kernel<<<grid, 256, MMA_SMEM>>>(o1, o2);
}

// round 8
// speedup vs baseline: 2.3091x; 1.5345x over previous
#include <cuda_runtime.h>
#include <cuda_bf16.h>
#include <cstdint>

#define S 128
#define C 32
#define NN 4096
#define T 512

extern __shared__ char dyn_smem[];

// ---------------- scratch (device globals; no allocation) ----------------
__device__ __align__(256) float g_P[S * NN];      // exp(log_softmax(emission))  [S,N]
__device__ __align__(256) float g_Tp[2][S * S];   // transition-power double buffer
__device__ __align__(256) float g_p[T * C * S];   // p_t = exp(h_t)              [T*C, S]
__device__ __align__(256) float g_wexp[T * C];    // exp(log_softmax(weights))   [T,C]
__device__ __align__(256) __nv_bfloat16 g_pA_hi[T * C * S];
__device__ __align__(256) __nv_bfloat16 g_pA_lo[T * C * S];
__device__ __align__(256) __nv_bfloat16 g_PT_hi[NN * S];   // P^T [n, s] K-contig
__device__ __align__(256) __nv_bfloat16 g_PT_lo[NN * S];

// ---------------- helpers ----------------
__device__ __forceinline__ uint32_t smem_u32(const void* p) {
    uint32_t a;
    asm("{ .reg .u64 t; cvta.to.shared.u64 t, %1; cvt.u32.u64 %0, t; }" : "=r"(a) : "l"(p));
    return a;
}
__device__ __forceinline__ void ldsm_x4(uint32_t addr, uint32_t& r0, uint32_t& r1,
                                        uint32_t& r2, uint32_t& r3) {
    asm volatile("ldmatrix.sync.aligned.m8n8.x4.shared.b16 {%0,%1,%2,%3}, [%4];"
                 : "=r"(r0), "=r"(r1), "=r"(r2), "=r"(r3) : "r"(addr));
}
__device__ __forceinline__ void mma16816(float* d, const uint32_t* a, const uint32_t* b) {
    asm volatile(
        "mma.sync.aligned.m16n8k16.row.col.f32.bf16.bf16.f32 "
        "{%0,%1,%2,%3},{%4,%5,%6,%7},{%8,%9},{%0,%1,%2,%3};"
        : "+f"(d[0]), "+f"(d[1]), "+f"(d[2]), "+f"(d[3])
        : "r"(a[0]), "r"(a[1]), "r"(a[2]), "r"(a[3]), "r"(b[0]), "r"(b[1]));
}
__device__ __forceinline__ void cp_async16(uint32_t dst, const void* src) {
    asm volatile("cp.async.cg.shared.global [%0], [%1], 16;" :: "r"(dst), "l"(src));
}
#define CP_COMMIT() asm volatile("cp.async.commit_group;" ::: "memory")
#define CP_WAIT(n)  asm volatile("cp.async.wait_group %0;" :: "n"(n) : "memory")

__device__ __forceinline__ float warpRedMax(float v) {
#pragma unroll
    for (int o = 16; o > 0; o >>= 1) v = fmaxf(v, __shfl_xor_sync(0xffffffffu, v, o));
    return v;
}
__device__ __forceinline__ float warpRedSum(float v) {
#pragma unroll
    for (int o = 16; o > 0; o >>= 1) v += __shfl_xor_sync(0xffffffffu, v, o);
    return v;
}

// ---------------- row-wise log_softmax (+optional exp to device-global) ----
__global__ void softmax_rows(const float* __restrict__ src, float* __restrict__ dlog,
                             int exp_dst, int ncols) {
    float* dexp = nullptr;
    if (exp_dst == 0) dexp = g_P;
    else if (exp_dst == 1) dexp = g_wexp;
    else if (exp_dst == 2) dexp = g_p;
    else if (exp_dst == 3) dexp = g_Tp[0];

    int row = blockIdx.x;
    const float* p = src + (size_t)row * ncols;
    int tid = threadIdx.x, lane = tid & 31, wid = tid >> 5;
    __shared__ float red[8];

    float m = -3.4e38f;
    for (int i = tid; i < ncols; i += blockDim.x) m = fmaxf(m, p[i]);
    m = warpRedMax(m);
    if (lane == 0) red[wid] = m;
    __syncthreads();
    if (wid == 0) {
        float v = (lane < 8) ? red[lane] : -3.4e38f;
        v = warpRedMax(v);
        if (lane == 0) red[0] = v;
    }
    __syncthreads();
    m = red[0];
    __syncthreads();

    float s = 0.f;
    for (int i = tid; i < ncols; i += blockDim.x) s += __expf(p[i] - m);
    s = warpRedSum(s);
    if (lane == 0) red[wid] = s;
    __syncthreads();
    if (wid == 0) {
        float v = (lane < 8) ? red[lane] : 0.f;
        v = warpRedSum(v);
        if (lane == 0) red[0] = v;
    }
    __syncthreads();
    float lse = m + __logf(red[0]);

    for (int i = tid; i < ncols; i += blockDim.x) {
        float v = p[i] - lse;
        if (dlog) dlog[(size_t)row * ncols + i] = v;
        if (dexp) dexp[(size_t)row * ncols + i] = __expf(v);
    }
}

// ---------------- doubling level (verified) ----------------
__global__ __launch_bounds__(256) void expand_level(int L, int curIdx) {
    float* smf = reinterpret_cast<float*>(dyn_smem);
    float* sA = smf;
    float* sB = smf + 32 * S;
    int tid = threadIdx.x, lane = tid & 31, wid = tid >> 5;
    int b = blockIdx.x;

    const float* Tcur = g_Tp[curIdx];
    float* Tnext = g_Tp[curIdx ^ 1];

    const float* A;
    float* O;
    if (b < L) {
        A = g_p + (size_t)b * C * S;
        O = g_p + (size_t)(L + b) * C * S;
    } else {
        int rb = b - L;
        A = Tcur + rb * 32 * S;
        O = Tnext + rb * 32 * S;
    }

    const float4* B4 = reinterpret_cast<const float4*>(Tcur);
    float4* sB4 = reinterpret_cast<float4*>(sB);
    for (int i = tid; i < S * S / 4; i += 256) sB4[i] = B4[i];
    const float4* A4 = reinterpret_cast<const float4*>(A);
    float4* sA4 = reinterpret_cast<float4*>(sA);
    for (int i = tid; i < 32 * S / 4; i += 256) sA4[i] = A4[i];
    __syncthreads();

    int c0 = wid * 4, n0 = lane * 4;
    float acc[4][4] = {};
#pragma unroll 8
    for (int s = 0; s < S; s++) {
        float4 bv = *reinterpret_cast<const float4*>(&sB[s * S + n0]);
#pragma unroll
        for (int j = 0; j < 4; j++) {
            float a = sA[(c0 + j) * S + s];
            acc[j][0] = fmaf(a, bv.x, acc[j][0]);
            acc[j][1] = fmaf(a, bv.y, acc[j][1]);
            acc[j][2] = fmaf(a, bv.z, acc[j][2]);
            acc[j][3] = fmaf(a, bv.w, acc[j][3]);
        }
    }
#pragma unroll
    for (int j = 0; j < 4; j++) {
        *reinterpret_cast<float4*>(&O[(c0 + j) * S + n0]) =
            make_float4(acc[j][0], acc[j][1], acc[j][2], acc[j][3]);
    }
}

// ---------------- fused postprocess: o3 = log(p) + hi/lo bf16 split ----------
__device__ __forceinline__ uint32_t pack2(float a, float b, float& ra, float& rb) {
    __nv_bfloat16 ha = __float2bfloat16_rn(a);
    __nv_bfloat16 hb = __float2bfloat16_rn(b);
    ra = a - __bfloat162float(ha);
    rb = b - __bfloat162float(hb);
    return (uint32_t)__bfloat16_as_ushort(ha) | ((uint32_t)__bfloat16_as_ushort(hb) << 16);
}
__global__ void postp(float* __restrict__ o3) {
    int i = blockIdx.x * blockDim.x + threadIdx.x;   // over T*C*S/4
    float4 v = reinterpret_cast<const float4*>(g_p)[i];
    reinterpret_cast<float4*>(o3)[i] =
        make_float4(__logf(v.x), __logf(v.y), __logf(v.z), __logf(v.w));
    float r0, r1, r2, r3;
    uint32_t h0 = pack2(v.x, v.y, r0, r1);
    uint32_t h1 = pack2(v.z, v.w, r2, r3);
    float d0, d1, d2, d3;
    uint32_t l0 = pack2(r0, r1, d0, d1);
    uint32_t l1 = pack2(r2, r3, d2, d3);
    reinterpret_cast<uint2*>(g_pA_hi)[i] = make_uint2(h0, h1);
    reinterpret_cast<uint2*>(g_pA_lo)[i] = make_uint2(l0, l1);
}

// ---------------- transpose P [S,N] -> PT hi/lo [N,S] ----------------
__global__ void transpose_P() {
    __shared__ float ts[32][33];
    int n0 = blockIdx.x * 32, s0 = blockIdx.y * 32;
    int tx = threadIdx.x, ty = threadIdx.y;   // (32, 8)
#pragma unroll
    for (int r = 0; r < 4; r++)
        ts[ty + r * 8][tx] = g_P[(size_t)(s0 + ty + r * 8) * NN + n0 + tx];
    __syncthreads();
#pragma unroll
    for (int r = 0; r < 4; r++) {
        int nloc = ty + r * 8;
        float x = ts[tx][nloc];
        __nv_bfloat16 h = __float2bfloat16_rn(x);
        __nv_bfloat16 l = __float2bfloat16_rn(x - __bfloat162float(h));
        size_t idx = (size_t)(n0 + nloc) * S + s0 + tx;
        g_PT_hi[idx] = h;
        g_PT_lo[idx] = l;
    }
}

// ---------------- mma.sync GEMM, cp.async pipelined, cached fragments -------
// CTA = (n-tile 128, t-quad). D = Ah*Bh + Ah*Bl + Al*Bh (fp32 regs).
// Warp w: rows 32*(w&3) x cols 64*(w>>2). Tiles: [Ah, Al, Bh, Bl], 272B pitch.
static constexpr int PITCH = 272;
static constexpr int TILE = 128 * PITCH;          // 34816
static constexpr int MMA_SMEM = 4 * TILE;         // 139264

__global__ __launch_bounds__(256, 1)
void mma_kernel(float* __restrict__ o1, float* __restrict__ o2) {
    char* sm = dyn_smem;
    uint32_t smb = smem_u32(sm);
    int tid = threadIdx.x, lane = tid & 31, wid = tid >> 5;
    int quad = blockIdx.y;
    int nb = blockIdx.x * 128;

    const uint4* srcA[4] = {
        reinterpret_cast<const uint4*>(g_pA_hi) + (size_t)quad * 128 * 16,
        reinterpret_cast<const uint4*>(g_pA_lo) + (size_t)quad * 128 * 16,
        reinterpret_cast<const uint4*>(g_PT_hi) + (size_t)nb * 16,
        reinterpret_cast<const uint4*>(g_PT_lo) + (size_t)nb * 16};

    // issue both K-half load stages up front (2 cp.async groups)
#pragma unroll
    for (int st = 0; st < 2; st++) {
#pragma unroll
        for (int j = 0; j < 16; j++) {
            int tile = j >> 2;                 // compile-time per j
            int w = tid + (j & 3) * 256;       // 0..1023
            int row = w >> 3, c = w & 7;
            uint32_t dst = smb + tile * TILE + row * PITCH + (st * 8 + c) * 16;
            cp_async16(dst, srcA[tile] + row * 16 + st * 8 + c);
        }
        CP_COMMIT();
    }

    int mbase = (wid & 3) * 32;
    int nbL = (wid >> 2) * 64;
    int aRow = mbase + (lane & 15);
    int aKoff = (lane >> 4) << 4;
    int bRow = nbL + ((lane >> 4) << 3) + (lane & 7);
    int bKoff = ((lane >> 3) & 1) << 4;

    float acc[2][8][4];
#pragma unroll
    for (int mt = 0; mt < 2; mt++)
#pragma unroll
        for (int nt = 0; nt < 8; nt++)
#pragma unroll
            for (int e = 0; e < 4; e++) acc[mt][nt][e] = 0.f;

    // compute one K-half (4 k16 steps) with fragment caching across passes
#pragma unroll
    for (int st = 0; st < 2; st++) {
        if (st == 0) { CP_WAIT(1); } else { CP_WAIT(0); }
        __syncthreads();
#pragma unroll
        for (int kk = 0; kk < 4; kk++) {
            int k16 = st * 4 + kk;
            uint32_t ah[2][4], al[2][4];
#pragma unroll
            for (int mt = 0; mt < 2; mt++) {
                ldsm_x4(smb + 0 * TILE + (aRow + mt * 16) * PITCH + k16 * 32 + aKoff,
                        ah[mt][0], ah[mt][1], ah[mt][2], ah[mt][3]);
                ldsm_x4(smb + 1 * TILE + (aRow + mt * 16) * PITCH + k16 * 32 + aKoff,
                        al[mt][0], al[mt][1], al[mt][2], al[mt][3]);
            }
            uint32_t bh[8][2], bl[8][2];
#pragma unroll
            for (int nt2 = 0; nt2 < 4; nt2++) {
                ldsm_x4(smb + 2 * TILE + (bRow + nt2 * 16) * PITCH + k16 * 32 + bKoff,
                        bh[nt2 * 2][0], bh[nt2 * 2][1], bh[nt2 * 2 + 1][0], bh[nt2 * 2 + 1][1]);
                ldsm_x4(smb + 3 * TILE + (bRow + nt2 * 16) * PITCH + k16 * 32 + bKoff,
                        bl[nt2 * 2][0], bl[nt2 * 2][1], bl[nt2 * 2 + 1][0], bl[nt2 * 2 + 1][1]);
            }
#pragma unroll
            for (int mt = 0; mt < 2; mt++)
#pragma unroll
                for (int nt = 0; nt < 8; nt++) {
                    mma16816(acc[mt][nt], ah[mt], bh[nt]);
                    mma16816(acc[mt][nt], ah[mt], bl[nt]);
                    mma16816(acc[mt][nt], al[mt], bh[nt]);
                }
        }
    }

    // ---- epilogue: logs + o2 stores + chain-weight reduction ----
    int t = quad * 4 + (wid & 3);
    float wlane = g_wexp[t * C + lane];
    int r0 = lane >> 2;
    int cq = lane & 3;

    float wr[2][2];
#pragma unroll
    for (int mt = 0; mt < 2; mt++) {
        wr[mt][0] = __shfl_sync(0xffffffffu, wlane, mt * 16 + r0);
        wr[mt][1] = __shfl_sync(0xffffffffu, wlane, mt * 16 + r0 + 8);
    }

#pragma unroll
    for (int nt = 0; nt < 8; nt++) {
        int ncol = nb + nbL + nt * 8 + cq * 2;
        float v0 = 0.f, v1 = 0.f;
#pragma unroll
        for (int mt = 0; mt < 2; mt++) {
            int c0 = mt * 16 + r0, c1 = c0 + 8;
            float2 s0 = make_float2(__logf(acc[mt][nt][0]), __logf(acc[mt][nt][1]));
            float2 s1 = make_float2(__logf(acc[mt][nt][2]), __logf(acc[mt][nt][3]));
            *reinterpret_cast<float2*>(&o2[((size_t)(t * C + c0)) * NN + ncol]) = s0;
            *reinterpret_cast<float2*>(&o2[((size_t)(t * C + c1)) * NN + ncol]) = s1;
            v0 += acc[mt][nt][0] * wr[mt][0] + acc[mt][nt][2] * wr[mt][1];
            v1 += acc[mt][nt][1] * wr[mt][0] + acc[mt][nt][3] * wr[mt][1];
        }
#pragma unroll
        for (int o = 4; o < 32; o <<= 1) {
            v0 += __shfl_xor_sync(0xffffffffu, v0, o);
            v1 += __shfl_xor_sync(0xffffffffu, v1, o);
        }
        if (lane < 4) {
            int n = nb + nbL + nt * 8 + lane * 2;
            *reinterpret_cast<float2*>(&o1[(size_t)t * NN + n]) =
                make_float2(__logf(v0), __logf(v1));
        }
    }
}

// ---------------- launch ----------------
extern "C" void kernel_launch(void* const* d_in, const int* in_sizes, int n_in,
                              void* d_out, int out_size) {
    (void)in_sizes; (void)n_in; (void)out_size;
    const float* init    = (const float*)d_in[0];   // [32,128]
    const float* weights = (const float*)d_in[1];   // [512,32]
    const float* emis    = (const float*)d_in[2];   // [128,4096]
    const float* trans   = (const float*)d_in[3];   // [128,128]

    float* out = (float*)d_out;
    float* o1 = out;                       // [512,4096]
    float* o2 = o1 + (size_t)T * NN;       // [512,32,4096]
    float* o3 = o2 + (size_t)T * C * NN;   // [512,32,128]
    float* o4 = o3 + (size_t)T * C * S;    // [128,4096]
    float* o5 = o4 + (size_t)S * NN;       // [512,32]

    const int expandSmem = (32 * S + S * S) * 4;   // 81920
    cudaFuncSetAttribute(expand_level, cudaFuncAttributeMaxDynamicSharedMemorySize, expandSmem);
    cudaFuncSetAttribute(mma_kernel, cudaFuncAttributeMaxDynamicSharedMemorySize, MMA_SMEM);

    // preprocess: log_softmax everything, exp() into device-global scratch
    softmax_rows<<<S, 256>>>(emis,    o4,      0, NN);   // g_P
    softmax_rows<<<T, 256>>>(weights, o5,      1, C);    // g_wexp
    softmax_rows<<<C, 256>>>(init,    nullptr, 2, S);    // g_p (p_0)
    softmax_rows<<<S, 256>>>(trans,   nullptr, 3, S);    // g_Tp[0]

    // P^T hi/lo (needs only emission softmax)
    transpose_P<<<dim3(NN / 32, S / 32), dim3(32, 8)>>>();

    // doubling recurrence: 9 levels
    for (int k = 0; k < 9; k++) {
        int L = 1 << k;
        int doSquare = (k < 8) ? 1 : 0;
        int grid = L + (doSquare ? 4 : 0);
        expand_level<<<grid, 256, expandSmem>>>(L, k & 1);
    }

    // fused: o3 = log(p), plus hi/lo split for the MMA
    postp<<<(T * C * S / 4) / 256, 256>>>(o3);

    // pipelined mma.sync GEMM + log epilogue (outputs 1, 2)
    dim3 grid(NN / 128, T / 4);
    mma_kernel<<<grid, 256, MMA_SMEM>>>(o1, o2);
}

// round 9
// speedup vs baseline: 2.5625x; 1.1097x over previous
#include <cuda_runtime.h>
#include <cuda_bf16.h>
#include <cstdint>

#define S 128
#define C 32
#define NN 4096
#define T 512

extern __shared__ char dyn_smem[];

// ---------------- scratch ----------------
__device__ __align__(256) float g_P[S * NN];      // exp(log_softmax(emission)) [S,N]
__device__ __align__(256) float g_Tp[2][S * S];   // transition-power double buffer
__device__ __align__(256) float g_p[T * C * S];   // p_t fp32 (recurrence-precision)
__device__ __align__(256) float g_pR[T * C * S];  // tf32-rounded copy for MMA
__device__ __align__(256) float g_wexp[T * C];    // exp(log_softmax(weights))
__device__ __align__(256) float g_PTR[NN * S];    // P^T tf32-rounded [n, s]

// ---------------- helpers ----------------
__device__ __forceinline__ uint32_t smem_u32(const void* p) {
    uint32_t a;
    asm("{ .reg .u64 t; cvta.to.shared.u64 t, %1; cvt.u32.u64 %0, t; }" : "=r"(a) : "l"(p));
    return a;
}
__device__ __forceinline__ void cp_async16(uint32_t dst, const void* src) {
    asm volatile("cp.async.cg.shared.global [%0], [%1], 16;" :: "r"(dst), "l"(src));
}
#define CP_COMMIT() asm volatile("cp.async.commit_group;" ::: "memory")
#define CP_WAIT(n)  asm volatile("cp.async.wait_group %0;" :: "n"(n) : "memory")

__device__ __forceinline__ float to_tf32(float x) {
    uint32_t u;
    asm("cvt.rna.tf32.f32 %0, %1;" : "=r"(u) : "f"(x));
    return __uint_as_float(u);
}
__device__ __forceinline__ void mma_tf32(float* d, const uint32_t* a, const uint32_t* b) {
    asm volatile(
        "mma.sync.aligned.m16n8k8.row.col.f32.tf32.tf32.f32 "
        "{%0,%1,%2,%3},{%4,%5,%6,%7},{%8,%9},{%0,%1,%2,%3};"
        : "+f"(d[0]), "+f"(d[1]), "+f"(d[2]), "+f"(d[3])
        : "r"(a[0]), "r"(a[1]), "r"(a[2]), "r"(a[3]), "r"(b[0]), "r"(b[1]));
}
__device__ __forceinline__ float warpRedMax(float v) {
#pragma unroll
    for (int o = 16; o > 0; o >>= 1) v = fmaxf(v, __shfl_xor_sync(0xffffffffu, v, o));
    return v;
}
__device__ __forceinline__ float warpRedSum(float v) {
#pragma unroll
    for (int o = 16; o > 0; o >>= 1) v += __shfl_xor_sync(0xffffffffu, v, o);
    return v;
}

// ---------------- fused log_softmax over all 4 inputs ----------------
// blocks [0,128): emission -> o4 + g_P
// blocks [128,640): weights -> o5 + g_wexp
// blocks [640,672): init -> o3 (t=0 rows) + g_p + g_pR
// blocks [672,800): trans -> g_Tp[0]
__global__ void softmax_all(const float* __restrict__ init, const float* __restrict__ weights,
                            const float* __restrict__ emis, const float* __restrict__ trans,
                            float* __restrict__ o3, float* __restrict__ o4, float* __restrict__ o5) {
    int b = blockIdx.x;
    const float* src;
    float* dlog = nullptr;
    float* dexp;
    float* dexpR = nullptr;
    int ncols;
    if (b < 128) {
        int row = b;
        src = emis + (size_t)row * NN;  ncols = NN;
        dlog = o4 + (size_t)row * NN;   dexp = g_P + (size_t)row * NN;
    } else if (b < 640) {
        int row = b - 128;
        src = weights + (size_t)row * C;  ncols = C;
        dlog = o5 + (size_t)row * C;      dexp = g_wexp + (size_t)row * C;
    } else if (b < 672) {
        int row = b - 640;
        src = init + (size_t)row * S;  ncols = S;
        dlog = o3 + (size_t)row * S;   dexp = g_p + (size_t)row * S;
        dexpR = g_pR + (size_t)row * S;
    } else {
        int row = b - 672;
        src = trans + (size_t)row * S;  ncols = S;
        dexp = g_Tp[0] + (size_t)row * S;
    }

    int tid = threadIdx.x, lane = tid & 31, wid = tid >> 5;
    __shared__ float red[8];

    float m = -3.4e38f;
    for (int i = tid; i < ncols; i += blockDim.x) m = fmaxf(m, src[i]);
    m = warpRedMax(m);
    if (lane == 0) red[wid] = m;
    __syncthreads();
    if (wid == 0) {
        float v = (lane < 8) ? red[lane] : -3.4e38f;
        v = warpRedMax(v);
        if (lane == 0) red[0] = v;
    }
    __syncthreads();
    m = red[0];
    __syncthreads();

    float s = 0.f;
    for (int i = tid; i < ncols; i += blockDim.x) s += __expf(src[i] - m);
    s = warpRedSum(s);
    if (lane == 0) red[wid] = s;
    __syncthreads();
    if (wid == 0) {
        float v = (lane < 8) ? red[lane] : 0.f;
        v = warpRedSum(v);
        if (lane == 0) red[0] = v;
    }
    __syncthreads();
    float lse = m + __logf(red[0]);

    for (int i = tid; i < ncols; i += blockDim.x) {
        float v = src[i] - lse;
        if (dlog) dlog[i] = v;
        float e = __expf(v);
        dexp[i] = e;
        if (dexpR) dexpR[i] = to_tf32(e);
    }
}

// ---------------- doubling level + fused o3/g_pR emission ----------------
__global__ __launch_bounds__(256) void expand_level(int L, int curIdx, float* __restrict__ o3) {
    float* smf = reinterpret_cast<float*>(dyn_smem);
    float* sA = smf;
    float* sB = smf + 32 * S;
    int tid = threadIdx.x, lane = tid & 31, wid = tid >> 5;
    int b = blockIdx.x;

    const float* Tcur = g_Tp[curIdx];
    float* Tnext = g_Tp[curIdx ^ 1];

    const float* A;
    float* O;
    bool isP = (b < L);
    size_t orow0 = 0;
    if (isP) {
        A = g_p + (size_t)b * C * S;
        O = g_p + (size_t)(L + b) * C * S;
        orow0 = (size_t)(L + b) * C;
    } else {
        int rb = b - L;
        A = Tcur + rb * 32 * S;
        O = Tnext + rb * 32 * S;
    }

    const float4* B4 = reinterpret_cast<const float4*>(Tcur);
    float4* sB4 = reinterpret_cast<float4*>(sB);
    for (int i = tid; i < S * S / 4; i += 256) sB4[i] = B4[i];
    const float4* A4 = reinterpret_cast<const float4*>(A);
    float4* sA4 = reinterpret_cast<float4*>(sA);
    for (int i = tid; i < 32 * S / 4; i += 256) sA4[i] = A4[i];
    __syncthreads();

    int c0 = wid * 4, n0 = lane * 4;
    float acc[4][4] = {};
#pragma unroll 8
    for (int s = 0; s < S; s++) {
        float4 bv = *reinterpret_cast<const float4*>(&sB[s * S + n0]);
#pragma unroll
        for (int j = 0; j < 4; j++) {
            float a = sA[(c0 + j) * S + s];
            acc[j][0] = fmaf(a, bv.x, acc[j][0]);
            acc[j][1] = fmaf(a, bv.y, acc[j][1]);
            acc[j][2] = fmaf(a, bv.z, acc[j][2]);
            acc[j][3] = fmaf(a, bv.w, acc[j][3]);
        }
    }
#pragma unroll
    for (int j = 0; j < 4; j++) {
        *reinterpret_cast<float4*>(&O[(c0 + j) * S + n0]) =
            make_float4(acc[j][0], acc[j][1], acc[j][2], acc[j][3]);
        if (isP) {
            size_t base = (orow0 + c0 + j) * S + n0;
            *reinterpret_cast<float4*>(&o3[base]) =
                make_float4(__logf(acc[j][0]), __logf(acc[j][1]),
                            __logf(acc[j][2]), __logf(acc[j][3]));
            *reinterpret_cast<float4*>(&g_pR[base]) =
                make_float4(to_tf32(acc[j][0]), to_tf32(acc[j][1]),
                            to_tf32(acc[j][2]), to_tf32(acc[j][3]));
        }
    }
}

// ---------------- transpose P [S,N] -> PTR tf32-rounded [N,S] ----------------
__global__ void transpose_P() {
    __shared__ float ts[32][33];
    int n0 = blockIdx.x * 32, s0 = blockIdx.y * 32;
    int tx = threadIdx.x, ty = threadIdx.y;   // (32, 8)
#pragma unroll
    for (int r = 0; r < 4; r++)
        ts[ty + r * 8][tx] = g_P[(size_t)(s0 + ty + r * 8) * NN + n0 + tx];
    __syncthreads();
#pragma unroll
    for (int r = 0; r < 4; r++) {
        int nloc = ty + r * 8;
        g_PTR[(size_t)(n0 + nloc) * S + s0 + tx] = to_tf32(ts[tx][nloc]);
    }
}

// ---------------- persistent tf32 GEMM + log epilogue ----------------
// grid = 128 CTAs, one quad (4 t-values = 128 M-rows) per CTA.
// A [128x128 fp32] resident in smem; 32 n-tiles streamed as 64 K-half chunks
// through a 3-slot cp.async ring. D = A @ B^T in one tf32 pass.
static constexpr int A_PW = 132;                   // words per A row (128+4 pad)
static constexpr int A_BYTES = 128 * A_PW * 4;     // 67584
static constexpr int B_PW = 68;                    // words per B half-row (64+4)
static constexpr int B_CHUNK = 128 * B_PW * 4;     // 34816
static constexpr int MMA_SMEM = A_BYTES + 3 * B_CHUNK;  // 172032

__global__ __launch_bounds__(256, 1)
void mma_kernel(float* __restrict__ o1, float* __restrict__ o2) {
    char* sm = dyn_smem;
    uint32_t smb = smem_u32(sm);
    int tid = threadIdx.x, lane = tid & 31, wid = tid >> 5;
    int quad = blockIdx.x;

    // prologue: resident A tile (128 rows x 512B)
    const uint4* srcA = reinterpret_cast<const uint4*>(g_pR) + (size_t)quad * 128 * 32;
#pragma unroll
    for (int j = 0; j < 16; j++) {
        int i = tid + j * 256;            // 0..4095
        int row = i >> 5, c = i & 31;
        cp_async16(smb + row * (A_PW * 4) + c * 16, srcA + row * 32 + c);
    }
    CP_COMMIT();

    auto issueB = [&](int chunk) {
        int tile = chunk >> 1, half = chunk & 1;
        const uint4* srcB = reinterpret_cast<const uint4*>(g_PTR)
                            + (size_t)tile * 128 * 32 + half * 16;
        uint32_t base = smb + A_BYTES + (chunk % 3) * B_CHUNK;
#pragma unroll
        for (int j = 0; j < 8; j++) {
            int i = tid + j * 256;        // 0..2047
            int row = i >> 4, c = i & 15;
            cp_async16(base + row * (B_PW * 4) + c * 16, srcB + row * 32 + c);
        }
    };
    issueB(0); CP_COMMIT();
    issueB(1); CP_COMMIT();
    issueB(2); CP_COMMIT();

    int mrow = (wid & 3) * 32 + (lane >> 2);
    int nrowBase = (wid >> 2) * 64 + (lane >> 2);
    int kt = lane & 3;
    int t = quad * 4 + (wid & 3);
    int r0 = lane >> 2, cq = lane & 3;
    float wlane = g_wexp[t * C + lane];
    float wr0  = __shfl_sync(0xffffffffu, wlane, r0);
    float wr0b = __shfl_sync(0xffffffffu, wlane, r0 + 8);
    float wr1  = __shfl_sync(0xffffffffu, wlane, 16 + r0);
    float wr1b = __shfl_sync(0xffffffffu, wlane, 16 + r0 + 8);

    const uint32_t* As = reinterpret_cast<const uint32_t*>(sm);
    float acc[2][8][4];

    for (int chunk = 0; chunk < 64; chunk++) {
        int tile = chunk >> 1, half = chunk & 1;
        CP_WAIT(2);
        __syncthreads();
        const uint32_t* Bs =
            reinterpret_cast<const uint32_t*>(sm + A_BYTES + (chunk % 3) * B_CHUNK);

        if (half == 0) {
#pragma unroll
            for (int mt = 0; mt < 2; mt++)
#pragma unroll
                for (int nt = 0; nt < 8; nt++)
#pragma unroll
                    for (int e = 0; e < 4; e++) acc[mt][nt][e] = 0.f;
        }

#pragma unroll
        for (int step = 0; step < 8; step++) {
            int k0 = half * 64 + step * 8 + kt;
            uint32_t a[2][4];
#pragma unroll
            for (int mt = 0; mt < 2; mt++) {
                int r = mrow + mt * 16;
                a[mt][0] = As[r * A_PW + k0];
                a[mt][1] = As[(r + 8) * A_PW + k0];
                a[mt][2] = As[r * A_PW + k0 + 4];
                a[mt][3] = As[(r + 8) * A_PW + k0 + 4];
            }
#pragma unroll
            for (int nt = 0; nt < 8; nt++) {
                int n = nrowBase + nt * 8;
                uint32_t bf[2];
                bf[0] = Bs[n * B_PW + step * 8 + kt];
                bf[1] = Bs[n * B_PW + step * 8 + kt + 4];
#pragma unroll
                for (int mt = 0; mt < 2; mt++) mma_tf32(acc[mt][nt], a[mt], bf);
            }
        }
        __syncthreads();
        if (chunk + 3 < 64) issueB(chunk + 3);
        CP_COMMIT();

        if (half == 1) {
            int nb = tile * 128;
            int nbL = (wid >> 2) * 64;
#pragma unroll
            for (int nt = 0; nt < 8; nt++) {
                int ncol = nb + nbL + nt * 8 + cq * 2;
                float v0, v1;
                {
                    float2 s0 = make_float2(__logf(acc[0][nt][0]), __logf(acc[0][nt][1]));
                    float2 s1 = make_float2(__logf(acc[0][nt][2]), __logf(acc[0][nt][3]));
                    *reinterpret_cast<float2*>(&o2[((size_t)(t * C + r0)) * NN + ncol]) = s0;
                    *reinterpret_cast<float2*>(&o2[((size_t)(t * C + r0 + 8)) * NN + ncol]) = s1;
                    v0 = acc[0][nt][0] * wr0 + acc[0][nt][2] * wr0b;
                    v1 = acc[0][nt][1] * wr0 + acc[0][nt][3] * wr0b;
                }
                {
                    float2 s0 = make_float2(__logf(acc[1][nt][0]), __logf(acc[1][nt][1]));
                    float2 s1 = make_float2(__logf(acc[1][nt][2]), __logf(acc[1][nt][3]));
                    *reinterpret_cast<float2*>(&o2[((size_t)(t * C + 16 + r0)) * NN + ncol]) = s0;
                    *reinterpret_cast<float2*>(&o2[((size_t)(t * C + 24 + r0)) * NN + ncol]) = s1;
                    v0 += acc[1][nt][0] * wr1 + acc[1][nt][2] * wr1b;
                    v1 += acc[1][nt][1] * wr1 + acc[1][nt][3] * wr1b;
                }
#pragma unroll
                for (int o = 4; o < 32; o <<= 1) {
                    v0 += __shfl_xor_sync(0xffffffffu, v0, o);
                    v1 += __shfl_xor_sync(0xffffffffu, v1, o);
                }
                if (lane < 4) {
                    int n = nb + nbL + nt * 8 + lane * 2;
                    *reinterpret_cast<float2*>(&o1[(size_t)t * NN + n]) =
                        make_float2(__logf(v0), __logf(v1));
                }
            }
        }
    }
}

// ---------------- launch ----------------
extern "C" void kernel_launch(void* const* d_in, const int* in_sizes, int n_in,
                              void* d_out, int out_size) {
    (void)in_sizes; (void)n_in; (void)out_size;
    const float* init    = (const float*)d_in[0];   // [32,128]
    const float* weights = (const float*)d_in[1];   // [512,32]
    const float* emis    = (const float*)d_in[2];   // [128,4096]
    const float* trans   = (const float*)d_in[3];   // [128,128]

    float* out = (float*)d_out;
    float* o1 = out;                       // [512,4096]
    float* o2 = o1 + (size_t)T * NN;       // [512,32,4096]
    float* o3 = o2 + (size_t)T * C * NN;   // [512,32,128]
    float* o4 = o3 + (size_t)T * C * S;    // [128,4096]
    float* o5 = o4 + (size_t)S * NN;       // [512,32]

    const int expandSmem = (32 * S + S * S) * 4;   // 81920
    cudaFuncSetAttribute(expand_level, cudaFuncAttributeMaxDynamicSharedMemorySize, expandSmem);
    cudaFuncSetAttribute(mma_kernel, cudaFuncAttributeMaxDynamicSharedMemorySize, MMA_SMEM);

    // one fused softmax pass over all four inputs
    softmax_all<<<800, 256>>>(init, weights, emis, trans, o3, o4, o5);

    // P^T tf32 (needs g_P)
    transpose_P<<<dim3(NN / 32, S / 32), dim3(32, 8)>>>();

    // doubling recurrence (emits o3 + g_pR inline)
    for (int k = 0; k < 9; k++) {
        int L = 1 << k;
        int doSquare = (k < 8) ? 1 : 0;
        int grid = L + (doSquare ? 4 : 0);
        expand_level<<<grid, 256, expandSmem>>>(L, k & 1, o3);
    }

    // persistent tf32 GEMM + log epilogue (outputs 1, 2)
    mma_kernel<<<128, 256, MMA_SMEM>>>(o1, o2);
}